// round 8
// baseline (speedup 1.0000x reference)
#include <cuda_runtime.h>

#define T_STEPS 512
#define IN_F 5
#define HDIM 7
#define TS 64
#define NTILE (T_STEPS / TS)
#define XROW (TS * IN_F + 12)   // 332 words: bank spread, float4-aligned
#define OROW (TS * 4 + 4)       // 260 words

typedef unsigned long long u64;

__device__ __forceinline__ float tanh_ap(float a) {
    float r; asm("tanh.approx.f32 %0, %1;" : "=f"(r) : "f"(a)); return r;
}
__device__ __forceinline__ u64 pk(float lo, float hi) {
    u64 r; asm("mov.b64 %0, {%1, %2};" : "=l"(r) : "f"(lo), "f"(hi)); return r;
}
__device__ __forceinline__ u64 pk1(float v) { return pk(v, v); }
__device__ __forceinline__ void up(u64 v, float& lo, float& hi) {
    asm("mov.b64 {%0, %1}, %2;" : "=f"(lo), "=f"(hi) : "l"(v));
}
__device__ __forceinline__ u64 f2(u64 a, u64 b, u64 c) {
    u64 d; asm("fma.rn.f32x2 %0, %1, %2, %3;" : "=l"(d) : "l"(a), "l"(b), "l"(c)); return d;
}
__device__ __forceinline__ u64 a2(u64 a, u64 b) {
    u64 d; asm("add.rn.f32x2 %0, %1, %2;" : "=l"(d) : "l"(a), "l"(b)); return d;
}

// 1 warp/CTA; warp = 8 groups x 4 lanes; each lane runs TWO independent chains
// (batches g and g+8), unit-pair packed lo/hi (unit 7 = zero-weight dummy).
__global__ void __launch_bounds__(32) gru_kernel(
    const float* __restrict__ x,
    const float* __restrict__ W_ih, const float* __restrict__ W_hh,
    const float* __restrict__ b_ih, const float* __restrict__ b_hh,
    const float* __restrict__ W_h0,
    const float* __restrict__ W_m, const float* __restrict__ b_m,
    const float* __restrict__ W_r, const float* __restrict__ b_r,
    float* __restrict__ out, int B)
{
    __shared__ float xs[16 * XROW];
    __shared__ float os[16 * OROW];

    int lane = threadIdx.x;
    int g = lane >> 2;
    int L = lane & 3;
    int b0 = blockIdx.x * 16 + g;       // chain 0 batch
    int b1 = b0 + 8;                    // chain 1 batch

    float* out_m = out;
    float* out_r = out + (size_t)B * T_STEPS * 3;
    float* out_h = out + (size_t)B * T_STEPS * 4;

    // ---- shared (single-copy) packed weights: lo = unit 2L, hi = unit 2L+1 ----
    u64 pwir[IN_F], pwiz[IN_F], pwin[IN_F];
    u64 pwhr[HDIM], pwhz[HDIM], pwhn[HDIM];
    u64 pbr, pbz, pbxn, pbhn;
    {
        int u0 = 2 * L, u1 = 2 * L + 1;
        bool v1 = (u1 < HDIM);
        int r0 = u0, z0 = HDIM + u0, n0 = 2 * HDIM + u0;
        int r1 = u1, z1 = HDIM + u1, n1 = 2 * HDIM + u1;
#pragma unroll
        for (int i = 0; i < IN_F; i++) {
            pwir[i] = pk(W_ih[r0 * IN_F + i], v1 ? W_ih[r1 * IN_F + i] : 0.f);
            pwiz[i] = pk(W_ih[z0 * IN_F + i], v1 ? W_ih[z1 * IN_F + i] : 0.f);
            pwin[i] = pk(W_ih[n0 * IN_F + i], v1 ? W_ih[n1 * IN_F + i] : 0.f);
        }
#pragma unroll
        for (int k = 0; k < HDIM; k++) {
            pwhr[k] = pk(W_hh[r0 * HDIM + k], v1 ? W_hh[r1 * HDIM + k] : 0.f);
            pwhz[k] = pk(W_hh[z0 * HDIM + k], v1 ? W_hh[z1 * HDIM + k] : 0.f);
            pwhn[k] = pk(W_hh[n0 * HDIM + k], v1 ? W_hh[n1 * HDIM + k] : 0.f);
        }
        pbr  = pk(b_ih[r0] + b_hh[r0], v1 ? (b_ih[r1] + b_hh[r1]) : 0.f);
        pbz  = pk(b_ih[z0] + b_hh[z0], v1 ? (b_ih[z1] + b_hh[z1]) : 0.f);
        pbxn = pk(b_ih[n0], v1 ? b_ih[n1] : 0.f);
        pbhn = pk(b_hh[n0], v1 ? b_hh[n1] : 0.f);
    }
    float wout[HDIM], ob;
#pragma unroll
    for (int k = 0; k < HDIM; k++)
        wout[k] = (L < 3) ? W_m[L * HDIM + k] : W_r[k];
    ob = (L < 3) ? b_m[L] : b_r[0];

    // ---- per-chain state ----
    float h0s[2], h1s[2];               // [chain]
    {
        int u0 = 2 * L, u1 = 2 * L + 1;
        bool v1 = (u1 < HDIM);
        float a = W_h0[u0], c = v1 ? W_h0[u1] : 0.f;
        h0s[0] = a; h0s[1] = a;
        h1s[0] = c; h1s[1] = c;
    }
    const float* xb[2] = { x + (size_t)b0 * T_STEPS * IN_F,
                           x + (size_t)b1 * T_STEPS * IN_F };
    float* xrow[2] = { xs + g * XROW, xs + (8 + g) * XROW };
    float* orow[2] = { os + g * OROW, os + (8 + g) * OROW };

    float hall[2][HDIM];
#pragma unroll
    for (int c = 0; c < 2; c++)
#pragma unroll
        for (int q = 0; q < 4; q++) {
            hall[c][2 * q] = __shfl_sync(0xffffffffu, h0s[c], q, 4);
            if (2 * q + 1 < HDIM)
                hall[c][2 * q + 1] = __shfl_sync(0xffffffffu, h1s[c], q, 4);
        }

    for (int tile = 0; tile < NTILE; tile++) {
        int t0 = tile * TS;

        // ---- stage x tiles for both chains (coalesced float4) ----
        __syncwarp();
#pragma unroll
        for (int c = 0; c < 2; c++) {
            const float4* src = (const float4*)(xb[c] + t0 * IN_F);
#pragma unroll
            for (int j = 0; j < (TS * IN_F) / 16; j++) {
                float4 v = src[L + 4 * j];
                *(float4*)(xrow[c] + (L + 4 * j) * 4) = v;
            }
        }
        __syncwarp();

        // ---- preamble: packed projection of x[t0] per chain ----
        u64 pxa_r[2], pxa_z[2], pxa_n[2];
#pragma unroll
        for (int c = 0; c < 2; c++) {
            u64 Ar = pbr, Az = pbz, An = pbxn;
#pragma unroll
            for (int i = 0; i < IN_F; i++) {
                u64 xi = pk1(xrow[c][i]);
                Ar = f2(pwir[i], xi, Ar);
                Az = f2(pwiz[i], xi, Az);
                An = f2(pwin[i], xi, An);
            }
            pxa_r[c] = Ar; pxa_z[c] = Az; pxa_n[c] = An;
        }

#pragma unroll 1
        for (int tt = 0; tt < TS; tt++) {
            int t1 = (tt + 1 < TS) ? (tt + 1) : (TS - 1);
            u64 pAr[2], pAz[2], pAn[2];

            // ---- packed gate dots over hall (both chains interleaved) ----
#pragma unroll
            for (int c = 0; c < 2; c++) {
                u64 ph[HDIM];
#pragma unroll
                for (int k = 0; k < HDIM; k++) ph[k] = pk1(hall[c][k]);
                u64 A0 = pxa_r[c], A1 = 0ULL;
                u64 Z0 = pxa_z[c], Z1 = 0ULL;
                u64 N0 = pbhn,     N1 = 0ULL;
#pragma unroll
                for (int k = 0; k < HDIM; k += 2) {
                    A0 = f2(pwhr[k], ph[k], A0);
                    Z0 = f2(pwhz[k], ph[k], Z0);
                    N0 = f2(pwhn[k], ph[k], N0);
                    if (k + 1 < HDIM) {
                        A1 = f2(pwhr[k + 1], ph[k + 1], A1);
                        Z1 = f2(pwhz[k + 1], ph[k + 1], Z1);
                        N1 = f2(pwhn[k + 1], ph[k + 1], N1);
                    }
                }
                pAr[c] = a2(A0, A1);
                pAz[c] = a2(Z0, Z1);
                pAn[c] = a2(N0, N1);
            }

            // ---- transcendentals + h updates (both chains) ----
#pragma unroll
            for (int c = 0; c < 2; c++) {
                float ar0, ar1, az0, az1, an0, an1, xn0, xn1;
                up(pAr[c], ar0, ar1); up(pAz[c], az0, az1);
                up(pAn[c], an0, an1); up(pxa_n[c], xn0, xn1);
                float r0 = fmaf(0.5f, tanh_ap(0.5f * ar0), 0.5f);
                float r1 = fmaf(0.5f, tanh_ap(0.5f * ar1), 0.5f);
                float z0 = fmaf(0.5f, tanh_ap(0.5f * az0), 0.5f);
                float z1 = fmaf(0.5f, tanh_ap(0.5f * az1), 0.5f);
                float n0 = tanh_ap(fmaf(r0, an0, xn0));
                float n1 = tanh_ap(fmaf(r1, an1, xn1));
                h0s[c] = fmaf(z0, h0s[c] - n0, n0);
                h1s[c] = fmaf(z1, h1s[c] - n1, n1);
            }

            // ---- gather h(t), heads, next projection (both chains) ----
#pragma unroll
            for (int c = 0; c < 2; c++) {
#pragma unroll
                for (int q = 0; q < 4; q++) {
                    hall[c][2 * q] = __shfl_sync(0xffffffffu, h0s[c], q, 4);
                    if (2 * q + 1 < HDIM)
                        hall[c][2 * q + 1] = __shfl_sync(0xffffffffu, h1s[c], q, 4);
                }
                float val = ob;
#pragma unroll
                for (int k = 0; k < HDIM; k++) val = fmaf(wout[k], hall[c][k], val);
                orow[c][tt * 4 + L] = val;

                u64 Ar = pbr, Az = pbz, An = pbxn;
#pragma unroll
                for (int i = 0; i < IN_F; i++) {
                    u64 xi = pk1(xrow[c][t1 * IN_F + i]);
                    Ar = f2(pwir[i], xi, Ar);
                    Az = f2(pwiz[i], xi, Az);
                    An = f2(pwin[i], xi, An);
                }
                pxa_r[c] = Ar; pxa_z[c] = Az; pxa_n[c] = An;
            }
        }
        __syncwarp();

        // ---- flush tiles (both chains) ----
#pragma unroll
        for (int c = 0; c < 2; c++) {
            int bb = (c == 0) ? b0 : b1;
            float* omg = out_m + (size_t)bb * T_STEPS * 3 + t0 * 3;
#pragma unroll
            for (int q = 0; q < 12; q++) {
                int p = (4 * q + L) * 4;
                float4 v;
                v.x = orow[c][((p + 0) / 3) * 4 + (p + 0) % 3];
                v.y = orow[c][((p + 1) / 3) * 4 + (p + 1) % 3];
                v.z = orow[c][((p + 2) / 3) * 4 + (p + 2) % 3];
                v.w = orow[c][((p + 3) / 3) * 4 + (p + 3) % 3];
                *(float4*)(omg + p) = v;
            }
            float* org = out_r + (size_t)bb * T_STEPS + t0;
#pragma unroll
            for (int q = 0; q < 4; q++) {
                int p = (4 * q + L) * 4;
                float4 v;
                v.x = orow[c][(p + 0) * 4 + 3];
                v.y = orow[c][(p + 1) * 4 + 3];
                v.z = orow[c][(p + 2) * 4 + 3];
                v.w = orow[c][(p + 3) * 4 + 3];
                *(float4*)(org + p) = v;
            }
        }
    }

    {
        int u0 = 2 * L, u1 = 2 * L + 1;
        out_h[(size_t)b0 * HDIM + u0] = h0s[0];
        out_h[(size_t)b1 * HDIM + u0] = h0s[1];
        if (u1 < HDIM) {
            out_h[(size_t)b0 * HDIM + u1] = h1s[0];
            out_h[(size_t)b1 * HDIM + u1] = h1s[1];
        }
    }
}

extern "C" void kernel_launch(void* const* d_in, const int* in_sizes, int n_in,
                              void* d_out, int out_size) {
    const float* x    = (const float*)d_in[0];
    const float* W_ih = (const float*)d_in[2];
    const float* W_hh = (const float*)d_in[3];
    const float* b_ih = (const float*)d_in[4];
    const float* b_hh = (const float*)d_in[5];
    const float* W_h0 = (const float*)d_in[6];
    const float* W_m  = (const float*)d_in[7];
    const float* b_m  = (const float*)d_in[8];
    const float* W_r  = (const float*)d_in[9];
    const float* b_r  = (const float*)d_in[10];

    int B = in_sizes[0] / (T_STEPS * IN_F);   // 8192
    int grid = (B + 15) / 16;                 // 16 batches per 1-warp CTA
    gru_kernel<<<grid, 32>>>(x, W_ih, W_hh, b_ih, b_hh, W_h0,
                             W_m, b_m, W_r, b_r, (float*)d_out, B);
}

// round 9
// speedup vs baseline: 1.1900x; 1.1900x over previous
#include <cuda_runtime.h>

#define T_STEPS 512
#define IN_F 5
#define HDIM 7
#define TS 64
#define NTILE (T_STEPS / TS)
#define XROW (TS * IN_F + 12)   // 332 words: bank spread, float4-aligned
#define OROW (TS * 4 + 4)       // 260 words

typedef unsigned long long u64;

__device__ __forceinline__ float tanh_ap(float a) {
    float r; asm("tanh.approx.f32 %0, %1;" : "=f"(r) : "f"(a)); return r;
}
__device__ __forceinline__ u64 pk(float lo, float hi) {
    u64 r; asm("mov.b64 %0, {%1, %2};" : "=l"(r) : "f"(lo), "f"(hi)); return r;
}
__device__ __forceinline__ u64 pk1(float v) { return pk(v, v); }
__device__ __forceinline__ void up(u64 v, float& lo, float& hi) {
    asm("mov.b64 {%0, %1}, %2;" : "=f"(lo), "=f"(hi) : "l"(v));
}
__device__ __forceinline__ u64 f2(u64 a, u64 b, u64 c) {
    u64 d; asm("fma.rn.f32x2 %0, %1, %2, %3;" : "=l"(d) : "l"(a), "l"(b), "l"(c)); return d;
}
__device__ __forceinline__ u64 a2(u64 a, u64 b) {
    u64 d; asm("add.rn.f32x2 %0, %1, %2;" : "=l"(d) : "l"(a), "l"(b)); return d;
}

// 1 warp/CTA; warp = 8 batches x 4 lanes. Lane L owns units {2L, 2L+1} packed lo/hi
// (unit 7 = zero-weight dummy). r/z pre-halved (sigma(a)=0.5+0.5 tanh(a/2));
// n-gate h-side pre-halved for r-elimination: n_arg = (xn+An') + tanh(ar')*An'.
__global__ void __launch_bounds__(32) gru_kernel(
    const float* __restrict__ x,
    const float* __restrict__ W_ih, const float* __restrict__ W_hh,
    const float* __restrict__ b_ih, const float* __restrict__ b_hh,
    const float* __restrict__ W_h0,
    const float* __restrict__ W_m, const float* __restrict__ b_m,
    const float* __restrict__ W_r, const float* __restrict__ b_r,
    float* __restrict__ out, int B)
{
    __shared__ float xs[8 * XROW];
    __shared__ float os[8 * OROW];

    int lane = threadIdx.x;
    int g = lane >> 2;
    int L = lane & 3;
    int b = blockIdx.x * 8 + g;

    float* out_m = out;
    float* out_r = out + (size_t)B * T_STEPS * 3;
    float* out_h = out + (size_t)B * T_STEPS * 4;

    // ---- packed per-lane weights (lo = unit 2L, hi = unit 2L+1) ----
    u64 pwir[IN_F], pwiz[IN_F], pwin[IN_F];   // r,z pre-halved; n unhalved
    u64 pwhr[HDIM], pwhz[HDIM], pwhn[HDIM];   // r,z,n h-side all pre-halved
    u64 pbr, pbz, pbxn, pbhn;
    float h0s, h1s;
    {
        int u0 = 2 * L, u1 = 2 * L + 1;
        bool v1 = (u1 < HDIM);
        int r0 = u0, z0 = HDIM + u0, n0 = 2 * HDIM + u0;
        int r1 = u1, z1 = HDIM + u1, n1 = 2 * HDIM + u1;
#pragma unroll
        for (int i = 0; i < IN_F; i++) {
            pwir[i] = pk(0.5f * W_ih[r0 * IN_F + i], v1 ? 0.5f * W_ih[r1 * IN_F + i] : 0.f);
            pwiz[i] = pk(0.5f * W_ih[z0 * IN_F + i], v1 ? 0.5f * W_ih[z1 * IN_F + i] : 0.f);
            pwin[i] = pk(W_ih[n0 * IN_F + i], v1 ? W_ih[n1 * IN_F + i] : 0.f);
        }
#pragma unroll
        for (int k = 0; k < HDIM; k++) {
            pwhr[k] = pk(0.5f * W_hh[r0 * HDIM + k], v1 ? 0.5f * W_hh[r1 * HDIM + k] : 0.f);
            pwhz[k] = pk(0.5f * W_hh[z0 * HDIM + k], v1 ? 0.5f * W_hh[z1 * HDIM + k] : 0.f);
            pwhn[k] = pk(0.5f * W_hh[n0 * HDIM + k], v1 ? 0.5f * W_hh[n1 * HDIM + k] : 0.f);
        }
        pbr  = pk(0.5f * (b_ih[r0] + b_hh[r0]), v1 ? 0.5f * (b_ih[r1] + b_hh[r1]) : 0.f);
        pbz  = pk(0.5f * (b_ih[z0] + b_hh[z0]), v1 ? 0.5f * (b_ih[z1] + b_hh[z1]) : 0.f);
        pbxn = pk(b_ih[n0], v1 ? b_ih[n1] : 0.f);
        pbhn = pk(0.5f * b_hh[n0], v1 ? 0.5f * b_hh[n1] : 0.f);
        h0s = W_h0[u0];
        h1s = v1 ? W_h0[u1] : 0.f;
    }
    float wout[HDIM], ob;
#pragma unroll
    for (int k = 0; k < HDIM; k++)
        wout[k] = (L < 3) ? W_m[L * HDIM + k] : W_r[k];
    ob = (L < 3) ? b_m[L] : b_r[0];

    const float* xb = x + (size_t)b * T_STEPS * IN_F;
    float* xrow = xs + g * XROW;
    float* orow = os + g * OROW;

    float hall[HDIM];
#pragma unroll
    for (int q = 0; q < 4; q++) {
        hall[2 * q] = __shfl_sync(0xffffffffu, h0s, q, 4);
        if (2 * q + 1 < HDIM)
            hall[2 * q + 1] = __shfl_sync(0xffffffffu, h1s, q, 4);
    }

    for (int tile = 0; tile < NTILE; tile++) {
        int t0 = tile * TS;

        // ---- stage x tile (coalesced float4) ----
        __syncwarp();
        const float4* src = (const float4*)(xb + t0 * IN_F);
#pragma unroll
        for (int j = 0; j < (TS * IN_F) / 16; j++) {
            float4 v = src[L + 4 * j];
            *(float4*)(xrow + (L + 4 * j) * 4) = v;
        }
        __syncwarp();

        // ---- preamble: packed projection of x[t0] ----
        u64 pxa_r, pxa_z, pxa_n;
        {
            u64 Ar = pbr, Az = pbz, An = pbxn;
#pragma unroll
            for (int i = 0; i < IN_F; i++) {
                u64 xi = pk1(xrow[i]);
                Ar = f2(pwir[i], xi, Ar);
                Az = f2(pwiz[i], xi, Az);
                An = f2(pwin[i], xi, An);
            }
            pxa_r = Ar; pxa_z = Az; pxa_n = An;
        }

#pragma unroll 2
        for (int tt = 0; tt < TS; tt++) {
            int t1 = (tt + 1 < TS) ? (tt + 1) : (TS - 1);

            // ---- packed gate dots over hall (2 accumulators) ----
            u64 ph[HDIM];
#pragma unroll
            for (int k = 0; k < HDIM; k++) ph[k] = pk1(hall[k]);

            u64 A0 = pxa_r, A1 = 0ULL;
            u64 Z0 = pxa_z, Z1 = 0ULL;
            u64 N0 = pbhn,  N1 = 0ULL;
#pragma unroll
            for (int k = 0; k < HDIM; k += 2) {
                A0 = f2(pwhr[k], ph[k], A0);
                Z0 = f2(pwhz[k], ph[k], Z0);
                N0 = f2(pwhn[k], ph[k], N0);
                if (k + 1 < HDIM) {
                    A1 = f2(pwhr[k + 1], ph[k + 1], A1);
                    Z1 = f2(pwhz[k + 1], ph[k + 1], Z1);
                    N1 = f2(pwhn[k + 1], ph[k + 1], N1);
                }
            }
            u64 pAn = a2(N0, N1);          // An' = 0.5*hn  (packed)
            u64 pc  = a2(pAn, pxa_n);      // c = xn + An'  (packed)

            float ar0, ar1, az0, az1, an0, an1, c0, c1;
            up(a2(A0, A1), ar0, ar1);
            up(a2(Z0, Z1), az0, az1);
            up(pAn, an0, an1);
            up(pc, c0, c1);

            // ---- gates: r eliminated; z via 0.5+0.5*tanh ----
            float tr0 = tanh_ap(ar0), tr1 = tanh_ap(ar1);
            float tz0 = tanh_ap(az0), tz1 = tanh_ap(az1);
            float n0 = tanh_ap(fmaf(tr0, an0, c0));
            float n1 = tanh_ap(fmaf(tr1, an1, c1));
            float z0 = fmaf(0.5f, tz0, 0.5f);
            float z1 = fmaf(0.5f, tz1, 0.5f);
            h0s = fmaf(z0, h0s - n0, n0);
            h1s = fmaf(z1, h1s - n1, n1);

            // ---- gather h(t) + heads ----
#pragma unroll
            for (int q = 0; q < 4; q++) {
                hall[2 * q] = __shfl_sync(0xffffffffu, h0s, q, 4);
                if (2 * q + 1 < HDIM)
                    hall[2 * q + 1] = __shfl_sync(0xffffffffu, h1s, q, 4);
            }
            float val = ob;
#pragma unroll
            for (int k = 0; k < HDIM; k++) val = fmaf(wout[k], hall[k], val);
            orow[tt * 4 + L] = val;

            // ---- packed projection for step t+1 (off critical path) ----
            {
                u64 Ar = pbr, Az = pbz, An = pbxn;
#pragma unroll
                for (int i = 0; i < IN_F; i++) {
                    u64 xi = pk1(xrow[t1 * IN_F + i]);
                    Ar = f2(pwir[i], xi, Ar);
                    Az = f2(pwiz[i], xi, Az);
                    An = f2(pwin[i], xi, An);
                }
                pxa_r = Ar; pxa_z = Az; pxa_n = An;
            }
        }
        __syncwarp();

        // ---- flush out_m tile ----
        float* omg = out_m + (size_t)b * T_STEPS * 3 + t0 * 3;
#pragma unroll
        for (int q = 0; q < 12; q++) {
            int p = (4 * q + L) * 4;
            float4 v;
            v.x = orow[((p + 0) / 3) * 4 + (p + 0) % 3];
            v.y = orow[((p + 1) / 3) * 4 + (p + 1) % 3];
            v.z = orow[((p + 2) / 3) * 4 + (p + 2) % 3];
            v.w = orow[((p + 3) / 3) * 4 + (p + 3) % 3];
            *(float4*)(omg + p) = v;
        }
        // ---- flush out_r tile ----
        float* org = out_r + (size_t)b * T_STEPS + t0;
#pragma unroll
        for (int q = 0; q < 4; q++) {
            int p = (4 * q + L) * 4;
            float4 v;
            v.x = orow[(p + 0) * 4 + 3];
            v.y = orow[(p + 1) * 4 + 3];
            v.z = orow[(p + 2) * 4 + 3];
            v.w = orow[(p + 3) * 4 + 3];
            *(float4*)(org + p) = v;
        }
    }

    {
        int u0 = 2 * L, u1 = 2 * L + 1;
        out_h[(size_t)b * HDIM + u0] = h0s;
        if (u1 < HDIM) out_h[(size_t)b * HDIM + u1] = h1s;
    }
}

extern "C" void kernel_launch(void* const* d_in, const int* in_sizes, int n_in,
                              void* d_out, int out_size) {
    const float* x    = (const float*)d_in[0];
    const float* W_ih = (const float*)d_in[2];
    const float* W_hh = (const float*)d_in[3];
    const float* b_ih = (const float*)d_in[4];
    const float* b_hh = (const float*)d_in[5];
    const float* W_h0 = (const float*)d_in[6];
    const float* W_m  = (const float*)d_in[7];
    const float* b_m  = (const float*)d_in[8];
    const float* W_r  = (const float*)d_in[9];
    const float* b_r  = (const float*)d_in[10];

    int B = in_sizes[0] / (T_STEPS * IN_F);   // 8192
    int grid = (B + 7) / 8;                   // 8 batches per 1-warp CTA
    gru_kernel<<<grid, 32>>>(x, W_ih, W_hh, b_ih, b_hh, W_h0,
                             W_m, b_m, W_r, b_r, (float*)d_out, B);
}

// round 10
// speedup vs baseline: 1.3703x; 1.1515x over previous
#include <cuda_runtime.h>

#define T_STEPS 512
#define IN_F 5
#define HDIM 7
#define TS 64
#define NTILE (T_STEPS / TS)
#define XROW (TS * IN_F + 12)   // 332 words: bank spread, float4-aligned
#define OROW (TS * 4 + 4)       // 260 words

typedef unsigned long long u64;

__device__ __forceinline__ float tanh_ap(float a) {
    float r; asm("tanh.approx.f32 %0, %1;" : "=f"(r) : "f"(a)); return r;
}
__device__ __forceinline__ u64 pk(float lo, float hi) {
    u64 r; asm("mov.b64 %0, {%1, %2};" : "=l"(r) : "f"(lo), "f"(hi)); return r;
}
__device__ __forceinline__ u64 pk1(float v) { return pk(v, v); }
__device__ __forceinline__ void up(u64 v, float& lo, float& hi) {
    asm("mov.b64 {%0, %1}, %2;" : "=f"(lo), "=f"(hi) : "l"(v));
}
__device__ __forceinline__ u64 f2(u64 a, u64 b, u64 c) {
    u64 d; asm("fma.rn.f32x2 %0, %1, %2, %3;" : "=l"(d) : "l"(a), "l"(b), "l"(c)); return d;
}
__device__ __forceinline__ u64 a2(u64 a, u64 b) {
    u64 d; asm("add.rn.f32x2 %0, %1, %2;" : "=l"(d) : "l"(a), "l"(b)); return d;
}

// 1 warp/CTA; warp = 8 batches x 4 lanes; lane L owns units {2L, 2L+1} packed lo/hi
// (unit 7 = zero-weight dummy). Identical structure to the 100.4us kernel
// (dist-2 register prefetch of x, unroll 2, in-loop heads); only the gate algebra
// changed: r/z weights pre-halved (sigma(a)=0.5+0.5 tanh(a')), n h-side pre-halved
// for r-elimination: n = tanh((xn + An') + tanh(ar')*An').
__global__ void __launch_bounds__(32) gru_kernel(
    const float* __restrict__ x,
    const float* __restrict__ W_ih, const float* __restrict__ W_hh,
    const float* __restrict__ b_ih, const float* __restrict__ b_hh,
    const float* __restrict__ W_h0,
    const float* __restrict__ W_m, const float* __restrict__ b_m,
    const float* __restrict__ W_r, const float* __restrict__ b_r,
    float* __restrict__ out, int B)
{
    __shared__ float xs[8 * XROW];
    __shared__ float os[8 * OROW];

    int lane = threadIdx.x;
    int g = lane >> 2;
    int L = lane & 3;
    int b = blockIdx.x * 8 + g;

    float* out_m = out;
    float* out_r = out + (size_t)B * T_STEPS * 3;
    float* out_h = out + (size_t)B * T_STEPS * 4;

    // ---- packed per-lane weights (lo = unit 2L, hi = unit 2L+1) ----
    u64 pwir[IN_F], pwiz[IN_F], pwin[IN_F];   // r,z pre-halved; n unhalved
    u64 pwhr[HDIM], pwhz[HDIM], pwhn[HDIM];   // all h-side pre-halved
    u64 pbr, pbz, pbxn, pbhn;
    float h0s, h1s;
    {
        int u0 = 2 * L, u1 = 2 * L + 1;
        bool v1 = (u1 < HDIM);
        int r0 = u0, z0 = HDIM + u0, n0 = 2 * HDIM + u0;
        int r1 = u1, z1 = HDIM + u1, n1 = 2 * HDIM + u1;
#pragma unroll
        for (int i = 0; i < IN_F; i++) {
            pwir[i] = pk(0.5f * W_ih[r0 * IN_F + i], v1 ? 0.5f * W_ih[r1 * IN_F + i] : 0.f);
            pwiz[i] = pk(0.5f * W_ih[z0 * IN_F + i], v1 ? 0.5f * W_ih[z1 * IN_F + i] : 0.f);
            pwin[i] = pk(W_ih[n0 * IN_F + i], v1 ? W_ih[n1 * IN_F + i] : 0.f);
        }
#pragma unroll
        for (int k = 0; k < HDIM; k++) {
            pwhr[k] = pk(0.5f * W_hh[r0 * HDIM + k], v1 ? 0.5f * W_hh[r1 * HDIM + k] : 0.f);
            pwhz[k] = pk(0.5f * W_hh[z0 * HDIM + k], v1 ? 0.5f * W_hh[z1 * HDIM + k] : 0.f);
            pwhn[k] = pk(0.5f * W_hh[n0 * HDIM + k], v1 ? 0.5f * W_hh[n1 * HDIM + k] : 0.f);
        }
        pbr  = pk(0.5f * (b_ih[r0] + b_hh[r0]), v1 ? 0.5f * (b_ih[r1] + b_hh[r1]) : 0.f);
        pbz  = pk(0.5f * (b_ih[z0] + b_hh[z0]), v1 ? 0.5f * (b_ih[z1] + b_hh[z1]) : 0.f);
        pbxn = pk(b_ih[n0], v1 ? b_ih[n1] : 0.f);
        pbhn = pk(0.5f * b_hh[n0], v1 ? 0.5f * b_hh[n1] : 0.f);
        h0s = W_h0[u0];
        h1s = v1 ? W_h0[u1] : 0.f;
    }
    float wout[HDIM], ob;
#pragma unroll
    for (int k = 0; k < HDIM; k++)
        wout[k] = (L < 3) ? W_m[L * HDIM + k] : W_r[k];
    ob = (L < 3) ? b_m[L] : b_r[0];

    const float* xb = x + (size_t)b * T_STEPS * IN_F;
    float* xrow = xs + g * XROW;
    float* orow = os + g * OROW;

    float hall[HDIM];
#pragma unroll
    for (int q = 0; q < 4; q++) {
        hall[2 * q] = __shfl_sync(0xffffffffu, h0s, q, 4);
        if (2 * q + 1 < HDIM)
            hall[2 * q + 1] = __shfl_sync(0xffffffffu, h1s, q, 4);
    }

    for (int tile = 0; tile < NTILE; tile++) {
        int t0 = tile * TS;

        // stage x tile (coalesced float4)
        __syncwarp();
        const float4* src = (const float4*)(xb + t0 * IN_F);
#pragma unroll
        for (int j = 0; j < (TS * IN_F) / 16; j++) {
            float4 v = src[L + 4 * j];
            *(float4*)(xrow + (L + 4 * j) * 4) = v;
        }
        __syncwarp();

        // preamble: packed projection of x[t0]; xvn = x[t0+1]
        u64 pxa_r, pxa_z, pxa_n;
        float xvn[IN_F];
        {
            u64 Ar = pbr, Az = pbz, An = pbxn;
#pragma unroll
            for (int i = 0; i < IN_F; i++) {
                u64 xi = pk1(xrow[i]);
                Ar = f2(pwir[i], xi, Ar);
                Az = f2(pwiz[i], xi, Az);
                An = f2(pwin[i], xi, An);
            }
            pxa_r = Ar; pxa_z = Az; pxa_n = An;
#pragma unroll
            for (int i = 0; i < IN_F; i++) xvn[i] = xrow[IN_F + i];
        }

#pragma unroll 2
        for (int tt = 0; tt < TS; tt++) {
            int t2 = (tt + 2 < TS) ? (tt + 2) : (TS - 1);
            float xv2[IN_F];
#pragma unroll
            for (int i = 0; i < IN_F; i++) xv2[i] = xrow[t2 * IN_F + i];

            // ---- packed gate dot-products over hall (2 accumulators) ----
            u64 ph[HDIM];
#pragma unroll
            for (int k = 0; k < HDIM; k++) ph[k] = pk1(hall[k]);

            u64 Ar0 = pxa_r, Ar1 = 0ULL;
            u64 Az0 = pxa_z, Az1 = 0ULL;
            u64 An0 = pbhn,  An1 = 0ULL;
#pragma unroll
            for (int k = 0; k < HDIM; k += 2) {
                Ar0 = f2(pwhr[k], ph[k], Ar0);
                Az0 = f2(pwhz[k], ph[k], Az0);
                An0 = f2(pwhn[k], ph[k], An0);
                if (k + 1 < HDIM) {
                    Ar1 = f2(pwhr[k + 1], ph[k + 1], Ar1);
                    Az1 = f2(pwhz[k + 1], ph[k + 1], Az1);
                    An1 = f2(pwhn[k + 1], ph[k + 1], An1);
                }
            }
            u64 pAn = a2(An0, An1);        // An' = 0.5*hn (packed)
            u64 pc  = a2(pAn, pxa_n);      // c = xn + An' (packed)

            // ---- gates: r eliminated, z via 0.5+0.5*tanh ----
            float ar0, ar1, az0, az1, an0, an1, c0, c1;
            up(a2(Ar0, Ar1), ar0, ar1);
            up(a2(Az0, Az1), az0, az1);
            up(pAn, an0, an1);
            up(pc, c0, c1);

            float tr0 = tanh_ap(ar0), tr1 = tanh_ap(ar1);
            float tz0 = tanh_ap(az0), tz1 = tanh_ap(az1);
            float n0 = tanh_ap(fmaf(tr0, an0, c0));
            float n1 = tanh_ap(fmaf(tr1, an1, c1));
            float z0 = fmaf(0.5f, tz0, 0.5f);
            float z1 = fmaf(0.5f, tz1, 0.5f);
            h0s = fmaf(z0, h0s - n0, n0);
            h1s = fmaf(z1, h1s - n1, n1);

            // ---- gather h(t) + heads ----
#pragma unroll
            for (int q = 0; q < 4; q++) {
                hall[2 * q] = __shfl_sync(0xffffffffu, h0s, q, 4);
                if (2 * q + 1 < HDIM)
                    hall[2 * q + 1] = __shfl_sync(0xffffffffu, h1s, q, 4);
            }
            float val = ob;
#pragma unroll
            for (int k = 0; k < HDIM; k++) val = fmaf(wout[k], hall[k], val);
            orow[tt * 4 + L] = val;

            // ---- packed projection for step t+1 (off critical path) ----
            {
                u64 Ar = pbr, Az = pbz, An = pbxn;
#pragma unroll
                for (int i = 0; i < IN_F; i++) {
                    u64 xi = pk1(xvn[i]);
                    Ar = f2(pwir[i], xi, Ar);
                    Az = f2(pwiz[i], xi, Az);
                    An = f2(pwin[i], xi, An);
                }
                pxa_r = Ar; pxa_z = Az; pxa_n = An;
            }
#pragma unroll
            for (int i = 0; i < IN_F; i++) xvn[i] = xv2[i];
        }
        __syncwarp();

        // ---- flush out_m tile ----
        float* omg = out_m + (size_t)b * T_STEPS * 3 + t0 * 3;
#pragma unroll
        for (int q = 0; q < 12; q++) {
            int p = (4 * q + L) * 4;
            float4 v;
            v.x = orow[((p + 0) / 3) * 4 + (p + 0) % 3];
            v.y = orow[((p + 1) / 3) * 4 + (p + 1) % 3];
            v.z = orow[((p + 2) / 3) * 4 + (p + 2) % 3];
            v.w = orow[((p + 3) / 3) * 4 + (p + 3) % 3];
            *(float4*)(omg + p) = v;
        }
        // ---- flush out_r tile ----
        float* org = out_r + (size_t)b * T_STEPS + t0;
#pragma unroll
        for (int q = 0; q < 4; q++) {
            int p = (4 * q + L) * 4;
            float4 v;
            v.x = orow[(p + 0) * 4 + 3];
            v.y = orow[(p + 1) * 4 + 3];
            v.z = orow[(p + 2) * 4 + 3];
            v.w = orow[(p + 3) * 4 + 3];
            *(float4*)(org + p) = v;
        }
    }

    {
        int u0 = 2 * L, u1 = 2 * L + 1;
        out_h[(size_t)b * HDIM + u0] = h0s;
        if (u1 < HDIM) out_h[(size_t)b * HDIM + u1] = h1s;
    }
}

extern "C" void kernel_launch(void* const* d_in, const int* in_sizes, int n_in,
                              void* d_out, int out_size) {
    const float* x    = (const float*)d_in[0];
    const float* W_ih = (const float*)d_in[2];
    const float* W_hh = (const float*)d_in[3];
    const float* b_ih = (const float*)d_in[4];
    const float* b_hh = (const float*)d_in[5];
    const float* W_h0 = (const float*)d_in[6];
    const float* W_m  = (const float*)d_in[7];
    const float* b_m  = (const float*)d_in[8];
    const float* W_r  = (const float*)d_in[9];
    const float* b_r  = (const float*)d_in[10];

    int B = in_sizes[0] / (T_STEPS * IN_F);   // 8192
    int grid = (B + 7) / 8;                   // 8 batches per 1-warp CTA
    gru_kernel<<<grid, 32>>>(x, W_ih, W_hh, b_ih, b_hh, W_h0,
                             W_m, b_m, W_r, b_r, (float*)d_out, B);
}